// round 7
// baseline (speedup 1.0000x reference)
#include <cuda_runtime.h>
#include <cstdint>

#define DIM        64
#define VECS       16                  // DIM/4 float4 per row
#define NBC        50000               // n_bicliques (fixed by problem)
#define NUSR_MAX   100000              // n_users upper bound

// Scratch (device globals: allowed; no allocation)
__device__ float g_biclique[NBC * DIM];   // 12.8 MB, accumulated UNNORMALIZED
__device__ float g_deg_v[NBC];            // becomes inv_deg after finalize
__device__ float g_deg_u[NUSR_MAX];

__device__ __forceinline__ void red_add_v4(float* dst, float4 v) {
    asm volatile("red.global.add.v4.f32 [%0], {%1,%2,%3,%4};"
                 :: "l"(dst), "f"(v.x), "f"(v.y), "f"(v.z), "f"(v.w)
                 : "memory");
}
__device__ __forceinline__ void red_add_f32(float* dst, float v) {
    asm volatile("red.global.add.f32 [%0], %1;"
                 :: "l"(dst), "f"(v)
                 : "memory");
}

// ---------------------------------------------------------------------------
// Zero all scratch + output (vectorized). All sizes are multiples of 4 floats.
// ---------------------------------------------------------------------------
__global__ void zero_all_kernel(float4* __restrict__ out, int out_v4) {
    int tid = blockIdx.x * blockDim.x + threadIdx.x;
    int stride = gridDim.x * blockDim.x;
    const float4 z = make_float4(0.f, 0.f, 0.f, 0.f);
    float4* bq = reinterpret_cast<float4*>(g_biclique);
    float4* dv = reinterpret_cast<float4*>(g_deg_v);
    float4* du = reinterpret_cast<float4*>(g_deg_u);
    for (int i = tid; i < NBC * VECS; i += stride)   bq[i] = z;
    for (int i = tid; i < NBC / 4; i += stride)      dv[i] = z;
    for (int i = tid; i < NUSR_MAX / 4; i += stride) du[i] = z;
    for (int i = tid; i < out_v4; i += stride)       out[i] = z;
}

// ---------------------------------------------------------------------------
// Stage-1 scatter: biclique[hv_rows[e]] += item_emb[hv_cols[e]], deg_v[r] += 1
// 16 threads per edge, one float4 each (256B coalesced gather per edge,
// 2 edges per warp). Feature scatter via REDG.v4 (no return trip).
// ---------------------------------------------------------------------------
__global__ void __launch_bounds__(256)
scatter1_kernel(const float4* __restrict__ item_emb,
                const int* __restrict__ rows,
                const int* __restrict__ cols,
                int nnz) {
    long long g = (long long)blockIdx.x * blockDim.x + threadIdx.x;
    int edge = (int)(g >> 4);
    int lane = (int)(g & 15);
    if (edge >= nnz) return;
    const int r = __ldg(&rows[edge]);
    const int c = __ldg(&cols[edge]);
    float4 v = item_emb[(long long)c * VECS + lane];
    red_add_v4(&g_biclique[(long long)r * DIM + lane * 4], v);
    if (lane == 8) red_add_f32(&g_deg_v[r], 1.0f);
}

// ---------------------------------------------------------------------------
// Finalize deg_v -> inverse degree (deg 0 -> 1). 50K threads, trivial.
// ---------------------------------------------------------------------------
__global__ void inv_deg_v_kernel() {
    int i = blockIdx.x * blockDim.x + threadIdx.x;
    if (i >= NBC) return;
    float d = g_deg_v[i];
    g_deg_v[i] = (d == 0.0f) ? 1.0f : (1.0f / d);
}

// ---------------------------------------------------------------------------
// Stage-2 scatter with fused stage-1 normalization:
//   out[hu_rows[e]] += biclique[hu_cols[e]] * inv_deg_v[hu_cols[e]]
//   deg_u[r] += 1
// ---------------------------------------------------------------------------
__global__ void __launch_bounds__(256)
scatter2_kernel(float* __restrict__ out,
                const int* __restrict__ rows,
                const int* __restrict__ cols,
                int nnz) {
    long long g = (long long)blockIdx.x * blockDim.x + threadIdx.x;
    int edge = (int)(g >> 4);
    int lane = (int)(g & 15);
    if (edge >= nnz) return;
    const int r = __ldg(&rows[edge]);
    const int c = __ldg(&cols[edge]);
    const float inv = __ldg(&g_deg_v[c]);    // finalized inverse degree
    const float4* bp = reinterpret_cast<const float4*>(g_biclique);
    float4 v = bp[(long long)c * VECS + lane];
    v.x *= inv; v.y *= inv; v.z *= inv; v.w *= inv;
    red_add_v4(&out[(long long)r * DIM + lane * 4], v);
    if (lane == 8) red_add_f32(&g_deg_u[r], 1.0f);
}

// ---------------------------------------------------------------------------
// Normalize output rows by deg_u (deg 0 -> 1). One float4 per thread.
// ---------------------------------------------------------------------------
__global__ void norm_out_kernel(float* __restrict__ out, int n_users) {
    int i = blockIdx.x * blockDim.x + threadIdx.x;
    if (i >= n_users * VECS) return;
    int row = i >> 4;
    float d = g_deg_u[row];
    float inv = (d == 0.0f) ? 1.0f : (1.0f / d);
    float4* p = reinterpret_cast<float4*>(out);
    float4 v = p[i];
    v.x *= inv; v.y *= inv; v.z *= inv; v.w *= inv;
    p[i] = v;
}

// ---------------------------------------------------------------------------
// Launch
// Inputs (metadata order): user_emb, item_emb, hv_rows, hv_cols, hu_rows,
//                          hu_cols, n_bicliques, n_users
// ---------------------------------------------------------------------------
extern "C" void kernel_launch(void* const* d_in, const int* in_sizes, int n_in,
                              void* d_out, int out_size) {
    const float4* item_emb = (const float4*)d_in[1];
    const int* hv_rows = (const int*)d_in[2];
    const int* hv_cols = (const int*)d_in[3];
    const int* hu_rows = (const int*)d_in[4];
    const int* hu_cols = (const int*)d_in[5];
    int nnz1 = in_sizes[2];
    int nnz2 = in_sizes[4];
    float* out = (float*)d_out;
    int n_users = out_size / DIM;

    // 1. zero scratch + out
    zero_all_kernel<<<1184, 256>>>(reinterpret_cast<float4*>(out), out_size / 4);

    // 2. stage-1 scatter
    {
        long long threads = (long long)nnz1 * 16;
        int blocks = (int)((threads + 255) / 256);
        scatter1_kernel<<<blocks, 256>>>(item_emb, hv_rows, hv_cols, nnz1);
    }

    // 3. finalize inverse degrees for bicliques
    inv_deg_v_kernel<<<(NBC + 255) / 256, 256>>>();

    // 4. stage-2 scatter (with fused stage-1 normalization)
    {
        long long threads = (long long)nnz2 * 16;
        int blocks = (int)((threads + 255) / 256);
        scatter2_kernel<<<blocks, 256>>>(out, hu_rows, hu_cols, nnz2);
    }

    // 5. normalize output
    {
        int n = n_users * VECS;
        norm_out_kernel<<<(n + 255) / 256, 256>>>(out, n_users);
    }
}

// round 15
// speedup vs baseline: 1.0512x; 1.0512x over previous
#include <cuda_runtime.h>
#include <cstdint>

#define DIM        64
#define VECS       16                  // DIM/4 float4 per row
#define NBC        50000               // n_bicliques (fixed by problem)
#define NUSR_MAX   100000              // n_users upper bound
#define EPT        4                   // edges per thread (MLP batching)

// Scratch (device globals: allowed; no allocation)
__device__ float g_biclique[NBC * DIM];   // 12.8 MB, accumulated UNNORMALIZED
__device__ float g_deg_v[NBC];            // becomes inv_deg after finalize
__device__ float g_deg_u[NUSR_MAX];

__device__ __forceinline__ void red_add_v4(float* dst, float4 v) {
    asm volatile("red.global.add.v4.f32 [%0], {%1,%2,%3,%4};"
                 :: "l"(dst), "f"(v.x), "f"(v.y), "f"(v.z), "f"(v.w)
                 : "memory");
}
__device__ __forceinline__ void red_add_f32(float* dst, float v) {
    asm volatile("red.global.add.f32 [%0], %1;"
                 :: "l"(dst), "f"(v)
                 : "memory");
}

// ---------------------------------------------------------------------------
// Zero all scratch + output (vectorized). All sizes are multiples of 4 floats.
// ---------------------------------------------------------------------------
__global__ void zero_all_kernel(float4* __restrict__ out, int out_v4) {
    int tid = blockIdx.x * blockDim.x + threadIdx.x;
    int stride = gridDim.x * blockDim.x;
    const float4 z = make_float4(0.f, 0.f, 0.f, 0.f);
    float4* bq = reinterpret_cast<float4*>(g_biclique);
    float4* dv = reinterpret_cast<float4*>(g_deg_v);
    float4* du = reinterpret_cast<float4*>(g_deg_u);
    for (int i = tid; i < NBC * VECS; i += stride)   bq[i] = z;
    for (int i = tid; i < NBC / 4; i += stride)      dv[i] = z;
    for (int i = tid; i < NUSR_MAX / 4; i += stride) du[i] = z;
    for (int i = tid; i < out_v4; i += stride)       out[i] = z;
}

// ---------------------------------------------------------------------------
// Stage-1 scatter, EPT edges per thread (front-batched loads for MLP):
//   biclique[hv_rows[e]] += item_emb[hv_cols[e]],  deg_v[r] += 1
// 16 lanes per edge-group, one float4 per lane; edges strided by ngroups so
// index loads stay warp-uniform broadcasts.
// ---------------------------------------------------------------------------
__global__ void __launch_bounds__(256)
scatter1_kernel(const float4* __restrict__ item_emb,
                const int* __restrict__ rows,
                const int* __restrict__ cols,
                int nnz, int ngroups) {
    int g = blockIdx.x * blockDim.x + threadIdx.x;
    int lane = g & 15;
    int eg = g >> 4;
    if (eg >= ngroups) return;

    int r[EPT], c[EPT];
    bool ok[EPT];
    #pragma unroll
    for (int k = 0; k < EPT; k++) {
        int e = eg + k * ngroups;
        ok[k] = (e < nnz);
        r[k] = ok[k] ? __ldg(&rows[e]) : 0;
        c[k] = ok[k] ? __ldg(&cols[e]) : 0;
    }
    float4 v[EPT];
    #pragma unroll
    for (int k = 0; k < EPT; k++)
        if (ok[k]) v[k] = item_emb[(long long)c[k] * VECS + lane];
    #pragma unroll
    for (int k = 0; k < EPT; k++)
        if (ok[k]) red_add_v4(&g_biclique[(long long)r[k] * DIM + lane * 4], v[k]);
    if (lane == 8) {
        #pragma unroll
        for (int k = 0; k < EPT; k++)
            if (ok[k]) red_add_f32(&g_deg_v[r[k]], 1.0f);
    }
}

// ---------------------------------------------------------------------------
// Finalize deg_v -> inverse degree (deg 0 -> 1). 50K threads, trivial.
// ---------------------------------------------------------------------------
__global__ void inv_deg_v_kernel() {
    int i = blockIdx.x * blockDim.x + threadIdx.x;
    if (i >= NBC) return;
    float d = g_deg_v[i];
    g_deg_v[i] = (d == 0.0f) ? 1.0f : (1.0f / d);
}

// ---------------------------------------------------------------------------
// Stage-2 scatter with fused stage-1 normalization, EPT edges per thread:
//   out[hu_rows[e]] += biclique[hu_cols[e]] * inv_deg_v[hu_cols[e]]
//   deg_u[r] += 1
// ---------------------------------------------------------------------------
__global__ void __launch_bounds__(256)
scatter2_kernel(float* __restrict__ out,
                const int* __restrict__ rows,
                const int* __restrict__ cols,
                int nnz, int ngroups) {
    int g = blockIdx.x * blockDim.x + threadIdx.x;
    int lane = g & 15;
    int eg = g >> 4;
    if (eg >= ngroups) return;

    int r[EPT], c[EPT];
    bool ok[EPT];
    #pragma unroll
    for (int k = 0; k < EPT; k++) {
        int e = eg + k * ngroups;
        ok[k] = (e < nnz);
        r[k] = ok[k] ? __ldg(&rows[e]) : 0;
        c[k] = ok[k] ? __ldg(&cols[e]) : 0;
    }
    float inv[EPT];
    #pragma unroll
    for (int k = 0; k < EPT; k++)
        inv[k] = ok[k] ? __ldg(&g_deg_v[c[k]]) : 0.f;
    const float4* bp = reinterpret_cast<const float4*>(g_biclique);
    float4 v[EPT];
    #pragma unroll
    for (int k = 0; k < EPT; k++)
        if (ok[k]) v[k] = bp[(long long)c[k] * VECS + lane];
    #pragma unroll
    for (int k = 0; k < EPT; k++) {
        if (ok[k]) {
            v[k].x *= inv[k]; v[k].y *= inv[k];
            v[k].z *= inv[k]; v[k].w *= inv[k];
            red_add_v4(&out[(long long)r[k] * DIM + lane * 4], v[k]);
        }
    }
    if (lane == 8) {
        #pragma unroll
        for (int k = 0; k < EPT; k++)
            if (ok[k]) red_add_f32(&g_deg_u[r[k]], 1.0f);
    }
}

// ---------------------------------------------------------------------------
// Normalize output rows by deg_u (deg 0 -> 1). One float4 per thread.
// ---------------------------------------------------------------------------
__global__ void norm_out_kernel(float* __restrict__ out, int n_users) {
    int i = blockIdx.x * blockDim.x + threadIdx.x;
    if (i >= n_users * VECS) return;
    int row = i >> 4;
    float d = g_deg_u[row];
    float inv = (d == 0.0f) ? 1.0f : (1.0f / d);
    float4* p = reinterpret_cast<float4*>(out);
    float4 v = p[i];
    v.x *= inv; v.y *= inv; v.z *= inv; v.w *= inv;
    p[i] = v;
}

// ---------------------------------------------------------------------------
// Launch
// Inputs (metadata order): user_emb, item_emb, hv_rows, hv_cols, hu_rows,
//                          hu_cols, n_bicliques, n_users
// ---------------------------------------------------------------------------
extern "C" void kernel_launch(void* const* d_in, const int* in_sizes, int n_in,
                              void* d_out, int out_size) {
    const float4* item_emb = (const float4*)d_in[1];
    const int* hv_rows = (const int*)d_in[2];
    const int* hv_cols = (const int*)d_in[3];
    const int* hu_rows = (const int*)d_in[4];
    const int* hu_cols = (const int*)d_in[5];
    int nnz1 = in_sizes[2];
    int nnz2 = in_sizes[4];
    float* out = (float*)d_out;
    int n_users = out_size / DIM;

    // 1. zero scratch + out
    zero_all_kernel<<<1184, 256>>>(reinterpret_cast<float4*>(out), out_size / 4);

    // 2. stage-1 scatter
    {
        int ngroups = (nnz1 + EPT - 1) / EPT;
        long long threads = (long long)ngroups * 16;
        int blocks = (int)((threads + 255) / 256);
        scatter1_kernel<<<blocks, 256>>>(item_emb, hv_rows, hv_cols, nnz1, ngroups);
    }

    // 3. finalize inverse degrees for bicliques
    inv_deg_v_kernel<<<(NBC + 255) / 256, 256>>>();

    // 4. stage-2 scatter (with fused stage-1 normalization)
    {
        int ngroups = (nnz2 + EPT - 1) / EPT;
        long long threads = (long long)ngroups * 16;
        int blocks = (int)((threads + 255) / 256);
        scatter2_kernel<<<blocks, 256>>>(out, hu_rows, hu_cols, nnz2, ngroups);
    }

    // 5. normalize output
    {
        int n = n_users * VECS;
        norm_out_kernel<<<(n + 255) / 256, 256>>>(out, n_users);
    }
}